// round 2
// baseline (speedup 1.0000x reference)
#include <cuda_runtime.h>
#include <cstdint>

// GraphHeteroAtt via legacy mma.sync (m16n8k8 tf32) — compute_103-safe (no tcgen05).
// U[n] = lrelu( (sum_k w_k[n] * H[k,n,:] @ Wuh[k]) / (sum_k w_k[n]) )
// w_k[n] = exp(lrelu( (H[k,n,:]@Wgh[k]) . (vt[n,:]@Wgv) ) / 8)

#define KH 8
#define HD 128
#define GD 64

// ---------------- helpers ----------------
__device__ __forceinline__ uint32_t smem_u32(const void* p) {
    uint32_t a;
    asm("{ .reg .u64 t; cvta.to.shared.u64 t, %1; cvt.u32.u64 %0, t; }"
        : "=r"(a) : "l"(p));
    return a;
}
__device__ __forceinline__ float tf32r(float x) {
    uint32_t u;
    asm("cvt.rna.tf32.f32 %0, %1;" : "=r"(u) : "f"(x));
    return __uint_as_float(u);
}
__device__ __forceinline__ uint32_t tf32u(float x) {
    uint32_t u;
    asm("cvt.rna.tf32.f32 %0, %1;" : "=r"(u) : "f"(x));
    return u;
}
__device__ __forceinline__ float4 tf32r4(float4 v) {
    v.x = tf32r(v.x); v.y = tf32r(v.y); v.z = tf32r(v.z); v.w = tf32r(v.w);
    return v;
}
__device__ __forceinline__ void sts128(uint32_t a, float4 v) {
    asm volatile("st.shared.v4.f32 [%0], {%1, %2, %3, %4};"
                 :: "r"(a), "f"(v.x), "f"(v.y), "f"(v.z), "f"(v.w) : "memory");
}
__device__ __forceinline__ float4 lds128(uint32_t a) {
    float4 v;
    asm volatile("ld.shared.v4.f32 {%0, %1, %2, %3}, [%4];"
                 : "=f"(v.x), "=f"(v.y), "=f"(v.z), "=f"(v.w) : "r"(a));
    return v;
}
__device__ __forceinline__ float lds32(uint32_t a) {
    float v;
    asm volatile("ld.shared.f32 %0, [%1];" : "=f"(v) : "r"(a));
    return v;
}
__device__ __forceinline__ void mma8(float c[4], const uint32_t a[4], uint32_t b0, uint32_t b1) {
    asm volatile(
        "mma.sync.aligned.m16n8k8.row.col.f32.tf32.tf32.f32 "
        "{%0,%1,%2,%3}, {%4,%5,%6,%7}, {%8,%9}, {%0,%1,%2,%3};"
        : "+f"(c[0]), "+f"(c[1]), "+f"(c[2]), "+f"(c[3])
        : "r"(a[0]), "r"(a[1]), "r"(a[2]), "r"(a[3]), "r"(b0), "r"(b1));
}

// ---------------- fragment-ordered weights ----------------
// B fragment for mma.m16n8k8 (B col-major, k x n = 8x8 tile):
//   lane (gid=lane>>2, tig=lane&3): b0 = B[tig][gid], b1 = B[tig+4][gid]
// Stored as float2 at index ((kt*NT + nt)*32 + lane).
__device__ float2 WgvF[4096];         // 16 kt * 8 nt * 32
__device__ float2 WghF[KH * 4096];
__device__ float2 WuhF[KH * 8192];    // 16 kt * 16 nt * 32

__global__ void prep_kernel(const float* __restrict__ Wgv,
                            const float* __restrict__ Wgh,
                            const float* __restrict__ Wuh) {
    int i = blockIdx.x * 256 + threadIdx.x;
    if (i < 4096) {
        int p = i;
        int kt = p >> 8, rem = p & 255, nt = rem >> 5, lane = rem & 31;
        int gid = lane >> 2, tig = lane & 3;
        int r0 = kt * 8 + tig, col = nt * 8 + gid;
        WgvF[p] = make_float2(tf32r(Wgv[r0 * GD + col]),
                              tf32r(Wgv[(r0 + 4) * GD + col]));
    } else if (i < 4096 + KH * 4096) {
        int j = i - 4096;
        int k = j >> 12, p = j & 4095;
        int kt = p >> 8, rem = p & 255, nt = rem >> 5, lane = rem & 31;
        int gid = lane >> 2, tig = lane & 3;
        int r0 = kt * 8 + tig, col = nt * 8 + gid;
        const float* b = Wgh + k * HD * GD;
        WghF[k * 4096 + p] = make_float2(tf32r(b[r0 * GD + col]),
                                         tf32r(b[(r0 + 4) * GD + col]));
    } else if (i < 4096 + KH * 4096 + KH * 8192) {
        int j = i - 4096 - KH * 4096;
        int k = j >> 13, p = j & 8191;
        int kt = p >> 9, rem = p & 511, nt = rem >> 5, lane = rem & 31;
        int gid = lane >> 2, tig = lane & 3;
        int r0 = kt * 8 + tig, col = nt * 8 + gid;
        const float* b = Wuh + k * HD * HD;
        WuhF[k * 8192 + p] = make_float2(tf32r(b[r0 * HD + col]),
                                         tf32r(b[(r0 + 4) * HD + col]));
    }
}

// ---------------- main kernel ----------------
// smem: A tile 128 rows x 132 floats (padded) = 67584 B; gk frags 32 KB.
#define ASTRIDE 132
#define SMEM_GK 67584u
#define SMEM_TOTAL (67584u + 32768u)

__global__ void __launch_bounds__(128)
het_main(const float* __restrict__ vt, const float* __restrict__ Hin,
         float* __restrict__ out, int Nn) {
    extern __shared__ char smem_raw[];
    const uint32_t A  = smem_u32(smem_raw);
    const uint32_t GK = A + SMEM_GK;

    const int tid  = threadIdx.x;
    const int warp = tid >> 5;
    const int lane = tid & 31;
    const int gid  = lane >> 2;
    const int tig  = lane & 3;
    const int base = blockIdx.x << 7;

    // ---- stage a 128x128 tile (rounded to tf32) ----
    auto stage = [&](const float4* src) {
#pragma unroll
        for (int j = 0; j < 32; j++) {
            int row = j * 4 + warp;
            int node = base + row;
            float4 v = make_float4(0.f, 0.f, 0.f, 0.f);
            if (node < Nn) v = src[(size_t)node * 32 + lane];
            sts128(A + (uint32_t)(row * ASTRIDE + lane * 4) * 4u, tf32r4(v));
        }
    };

    // raw A fragment (rows r0+gid / r0+gid+8, cols c..c+4)
    auto ldaf = [&](float f[4], int r0, int c) {
        uint32_t p = A + (uint32_t)((r0 + gid) * ASTRIDE + c + tig) * 4u;
        f[0] = lds32(p);
        f[1] = lds32(p + 8u * ASTRIDE * 4u);
        f[2] = lds32(p + 16u);
        f[3] = lds32(p + 8u * ASTRIDE * 4u + 16u);
    };

    // ---------------- prologue: gk = vt @ Wgv, park fragments in smem ----------------
    stage((const float4*)vt);
    __syncthreads();
#pragma unroll
    for (int mt = 0; mt < 2; mt++) {
        const int r0 = warp * 32 + mt * 16;
#pragma unroll
        for (int half = 0; half < 2; half++) {
            float c[4][4];
#pragma unroll
            for (int n = 0; n < 4; n++)
#pragma unroll
                for (int q = 0; q < 4; q++) c[n][q] = 0.f;
#pragma unroll
            for (int kt = 0; kt < 16; kt++) {
                float fa[4]; ldaf(fa, r0, kt * 8);
                uint32_t a[4] = { __float_as_uint(fa[0]), __float_as_uint(fa[1]),
                                  __float_as_uint(fa[2]), __float_as_uint(fa[3]) };
                const float2* bp = WgvF + (kt * 8 + half * 4) * 32 + lane;
#pragma unroll
                for (int n = 0; n < 4; n++) {
                    float2 b = __ldg(bp + n * 32);
                    mma8(c[n], a, __float_as_uint(b.x), __float_as_uint(b.y));
                }
            }
#pragma unroll
            for (int n = 0; n < 4; n++) {
                int i = mt * 8 + half * 4 + n;
                sts128(GK + (uint32_t)(i * 128 + tid) * 16u,
                       make_float4(c[n][0], c[n][1], c[n][2], c[n][3]));
            }
        }
    }

    // ---------------- main loop over relations ----------------
    float uacc[2][16][4];
#pragma unroll
    for (int mt = 0; mt < 2; mt++)
#pragma unroll
        for (int n = 0; n < 16; n++)
#pragma unroll
            for (int q = 0; q < 4; q++) uacc[mt][n][q] = 0.f;
    float Z[2][2] = {{0.f, 0.f}, {0.f, 0.f}};

    for (int k = 0; k < KH; k++) {
        __syncthreads();
        stage((const float4*)(Hin + (size_t)k * (size_t)Nn * HD));
        __syncthreads();

        // ---- GEMM1 (gq) + dot with gk -> w per row ----
        float w[2][2];
#pragma unroll
        for (int mt = 0; mt < 2; mt++) {
            const int r0 = warp * 32 + mt * 16;
            float d0 = 0.f, d1 = 0.f;
#pragma unroll
            for (int half = 0; half < 2; half++) {
                float c[4][4];
#pragma unroll
                for (int n = 0; n < 4; n++)
#pragma unroll
                    for (int q = 0; q < 4; q++) c[n][q] = 0.f;
#pragma unroll
                for (int kt = 0; kt < 16; kt++) {
                    float fa[4]; ldaf(fa, r0, kt * 8);
                    uint32_t a[4] = { __float_as_uint(fa[0]), __float_as_uint(fa[1]),
                                      __float_as_uint(fa[2]), __float_as_uint(fa[3]) };
                    const float2* bp = WghF + k * 4096 + (kt * 8 + half * 4) * 32 + lane;
#pragma unroll
                    for (int n = 0; n < 4; n++) {
                        float2 b = __ldg(bp + n * 32);
                        mma8(c[n], a, __float_as_uint(b.x), __float_as_uint(b.y));
                    }
                }
#pragma unroll
                for (int n = 0; n < 4; n++) {
                    int i = mt * 8 + half * 4 + n;
                    float4 g = lds128(GK + (uint32_t)(i * 128 + tid) * 16u);
                    d0 = fmaf(c[n][0], g.x, fmaf(c[n][1], g.y, d0));
                    d1 = fmaf(c[n][2], g.z, fmaf(c[n][3], g.w, d1));
                }
            }
            d0 += __shfl_xor_sync(0xffffffffu, d0, 1);
            d0 += __shfl_xor_sync(0xffffffffu, d0, 2);
            d1 += __shfl_xor_sync(0xffffffffu, d1, 1);
            d1 += __shfl_xor_sync(0xffffffffu, d1, 2);
            float l0 = d0 >= 0.f ? d0 : 0.01f * d0;
            float l1 = d1 >= 0.f ? d1 : 0.01f * d1;
            w[mt][0] = __expf(l0 * 0.125f);
            w[mt][1] = __expf(l1 * 0.125f);
            Z[mt][0] += w[mt][0];
            Z[mt][1] += w[mt][1];
        }

        // ---- GEMM2: U += (w .* H) @ Wuh[k] ----
#pragma unroll
        for (int kt = 0; kt < 16; kt++) {
            uint32_t a0[4], a1[4];
            {
                float f[4]; ldaf(f, warp * 32, kt * 8);
                a0[0] = tf32u(f[0] * w[0][0]); a0[1] = tf32u(f[1] * w[0][1]);
                a0[2] = tf32u(f[2] * w[0][0]); a0[3] = tf32u(f[3] * w[0][1]);
            }
            {
                float f[4]; ldaf(f, warp * 32 + 16, kt * 8);
                a1[0] = tf32u(f[0] * w[1][0]); a1[1] = tf32u(f[1] * w[1][1]);
                a1[2] = tf32u(f[2] * w[1][0]); a1[3] = tf32u(f[3] * w[1][1]);
            }
            const float2* bp = WuhF + k * 8192 + kt * 16 * 32 + lane;
#pragma unroll
            for (int n = 0; n < 16; n++) {
                float2 b = __ldg(bp + n * 32);
                uint32_t b0 = __float_as_uint(b.x), b1 = __float_as_uint(b.y);
                mma8(uacc[0][n], a0, b0, b1);
                mma8(uacc[1][n], a1, b0, b1);
            }
        }
    }

    // ---------------- epilogue ----------------
#pragma unroll
    for (int mt = 0; mt < 2; mt++) {
        float inv0 = 1.0f / Z[mt][0];
        float inv1 = 1.0f / Z[mt][1];
        int node0 = base + warp * 32 + mt * 16 + gid;
        int node1 = node0 + 8;
        if (node0 < Nn) {
            float2* op = (float2*)(out + (size_t)node0 * HD);
#pragma unroll
            for (int n = 0; n < 16; n++) {
                float v0 = uacc[mt][n][0] * inv0;
                float v1 = uacc[mt][n][1] * inv0;
                float2 o;
                o.x = v0 >= 0.f ? v0 : 0.01f * v0;
                o.y = v1 >= 0.f ? v1 : 0.01f * v1;
                op[n * 4 + tig] = o;
            }
        }
        if (node1 < Nn) {
            float2* op = (float2*)(out + (size_t)node1 * HD);
#pragma unroll
            for (int n = 0; n < 16; n++) {
                float v0 = uacc[mt][n][2] * inv1;
                float v1 = uacc[mt][n][3] * inv1;
                float2 o;
                o.x = v0 >= 0.f ? v0 : 0.01f * v0;
                o.y = v1 >= 0.f ? v1 : 0.01f * v1;
                op[n * 4 + tig] = o;
            }
        }
    }
}

// ---------------- launch ----------------
extern "C" void kernel_launch(void* const* d_in, const int* in_sizes, int n_in,
                              void* d_out, int out_size) {
    const float* vt  = (const float*)d_in[0];
    const float* H   = (const float*)d_in[1];
    const float* Wgv = (const float*)d_in[2];
    const float* Wgh = (const float*)d_in[3];
    const float* Wuh = (const float*)d_in[4];
    float* out = (float*)d_out;

    int Nn = in_sizes[0] / HD;

    cudaFuncSetAttribute(het_main, cudaFuncAttributeMaxDynamicSharedMemorySize, SMEM_TOTAL);

    int total = 4096 + KH * 4096 + KH * 8192;  // 102400 float2 outputs
    prep_kernel<<<(total + 255) / 256, 256>>>(Wgv, Wgh, Wuh);

    int blocks = (Nn + 127) / 128;
    het_main<<<blocks, 128, SMEM_TOTAL>>>(vt, H, out, Nn);
}

// round 3
// speedup vs baseline: 2.1020x; 2.1020x over previous
#include <cuda_runtime.h>
#include <cstdint>

// GraphHeteroAtt via mma.sync m16n8k8 tf32 (compute_103-safe).
// U[n] = lrelu( (sum_k w_k[n] * H[k,n,:] @ Wuh[k]) / (sum_k w_k[n]) )
// w_k[n] = exp(lrelu( (H[k,n,:]@Wgh[k]) . (vt[n,:]@Wgv) ) / 8)
//
// CTA = 128 nodes, 256 threads (8 warps). Warp pair (w, w+4) owns rows
// (w&3)*32..+31 (two m16 tiles); warp w computes output-column half (w>>2).
// H tiles double-buffered via cp.async.cg. gk fragments register-resident.

#define KH 8
#define HD 128
#define GD 64
#define ASTRIDE 132           // floats per padded row

// ---------------- helpers ----------------
__device__ __forceinline__ uint32_t smem_u32(const void* p) {
    uint32_t a;
    asm("{ .reg .u64 t; cvta.to.shared.u64 t, %1; cvt.u32.u64 %0, t; }"
        : "=r"(a) : "l"(p));
    return a;
}
__device__ __forceinline__ float tf32r(float x) {
    uint32_t u;
    asm("cvt.rna.tf32.f32 %0, %1;" : "=r"(u) : "f"(x));
    return __uint_as_float(u);
}
__device__ __forceinline__ uint32_t tf32u(float x) {
    uint32_t u;
    asm("cvt.rna.tf32.f32 %0, %1;" : "=r"(u) : "f"(x));
    return u;
}
__device__ __forceinline__ void sts128(uint32_t a, float4 v) {
    asm volatile("st.shared.v4.f32 [%0], {%1, %2, %3, %4};"
                 :: "r"(a), "f"(v.x), "f"(v.y), "f"(v.z), "f"(v.w) : "memory");
}
__device__ __forceinline__ void sts32(uint32_t a, float v) {
    asm volatile("st.shared.f32 [%0], %1;" :: "r"(a), "f"(v) : "memory");
}
__device__ __forceinline__ float lds32(uint32_t a) {
    float v;
    asm volatile("ld.shared.f32 %0, [%1];" : "=f"(v) : "r"(a));
    return v;
}
__device__ __forceinline__ void mma8(float c[4], const uint32_t a[4], uint32_t b0, uint32_t b1) {
    asm volatile(
        "mma.sync.aligned.m16n8k8.row.col.f32.tf32.tf32.f32 "
        "{%0,%1,%2,%3}, {%4,%5,%6,%7}, {%8,%9}, {%0,%1,%2,%3};"
        : "+f"(c[0]), "+f"(c[1]), "+f"(c[2]), "+f"(c[3])
        : "r"(a[0]), "r"(a[1]), "r"(a[2]), "r"(a[3]), "r"(b0), "r"(b1));
}

// ---------------- fragment-ordered weights ----------------
// B frag (m16n8k8, col-major B, 8x8 k-x-n tile): lane(gid=lane>>2,tig=lane&3):
//   b0 = B[tig][gid], b1 = B[tig+4][gid]; stored float2 at ((kt*NT+nt)*32+lane).
__device__ float2 WgvF[4096];         // 16 kt * 8 nt * 32
__device__ float2 WghF[KH * 4096];
__device__ float2 WuhF[KH * 8192];    // 16 kt * 16 nt * 32

__global__ void prep_kernel(const float* __restrict__ Wgv,
                            const float* __restrict__ Wgh,
                            const float* __restrict__ Wuh) {
    int i = blockIdx.x * 256 + threadIdx.x;
    if (i < 4096) {
        int p = i;
        int kt = p >> 8, rem = p & 255, nt = rem >> 5, lane = rem & 31;
        int gid = lane >> 2, tig = lane & 3;
        int r0 = kt * 8 + tig, col = nt * 8 + gid;
        WgvF[p] = make_float2(tf32r(Wgv[r0 * GD + col]),
                              tf32r(Wgv[(r0 + 4) * GD + col]));
    } else if (i < 4096 + KH * 4096) {
        int j = i - 4096;
        int k = j >> 12, p = j & 4095;
        int kt = p >> 8, rem = p & 255, nt = rem >> 5, lane = rem & 31;
        int gid = lane >> 2, tig = lane & 3;
        int r0 = kt * 8 + tig, col = nt * 8 + gid;
        const float* b = Wgh + k * HD * GD;
        WghF[k * 4096 + p] = make_float2(tf32r(b[r0 * GD + col]),
                                         tf32r(b[(r0 + 4) * GD + col]));
    } else if (i < 4096 + KH * 4096 + KH * 8192) {
        int j = i - 4096 - KH * 4096;
        int k = j >> 13, p = j & 8191;
        int kt = p >> 9, rem = p & 511, nt = rem >> 5, lane = rem & 31;
        int gid = lane >> 2, tig = lane & 3;
        int r0 = kt * 8 + tig, col = nt * 8 + gid;
        const float* b = Wuh + k * HD * HD;
        WuhF[k * 8192 + p] = make_float2(tf32r(b[r0 * HD + col]),
                                         tf32r(b[(r0 + 4) * HD + col]));
    }
}

// ---------------- smem layout ----------------
// A0 @ 0        : 128 x 132 f32 = 67584 B
// A1 @ 67584    : 67584 B
// DS @ 135168   : 2 x 128 f32 partial dots = 1024 B
#define ABUF_BYTES 67584u
#define SMEM_DS    135168u
#define SMEM_TOTAL 136192u

__global__ void __launch_bounds__(256)
het_main(const float* __restrict__ vt, const float* __restrict__ Hin,
         float* __restrict__ out, int Nn) {
    extern __shared__ char smem_raw[];
    const uint32_t A0 = smem_u32(smem_raw);
    const uint32_t A1 = A0 + ABUF_BYTES;
    const uint32_t DS = A0 + SMEM_DS;

    const int tid   = threadIdx.x;
    const int warp  = tid >> 5;
    const int lane  = tid & 31;
    const int gid   = lane >> 2;
    const int tig   = lane & 3;
    const int wrow  = warp & 3;       // row group 0..3 (32 rows each)
    const int nhalf = warp >> 2;      // output-column half
    const int base  = blockIdx.x << 7;

    // async prefetch of one 128x128 tile (raw f32) into buffer Ab
    auto prefetch = [&](uint32_t Ab, const float* src) {
#pragma unroll
        for (int j = 0; j < 16; j++) {
            int idx = j * 256 + tid;
            int row = idx >> 5, ch = idx & 31;
            int node = base + row;
            const float* s = src + (size_t)(node < Nn ? node : 0) * HD + ch * 4;
            uint32_t d = Ab + (uint32_t)(row * ASTRIDE + ch * 4) * 4u;
            int sz = (node < Nn) ? 16 : 0;
            asm volatile("cp.async.cg.shared.global [%0], [%1], 16, %2;"
                         :: "r"(d), "l"(s), "r"(sz) : "memory");
        }
        asm volatile("cp.async.commit_group;" ::: "memory");
    };

    // raw A fragment: rows r0+gid / r0+gid+8, cols c+tig / c+tig+4(x2 via k halves)
    auto ldaf = [&](float f[4], uint32_t Ab, int r0, int c) {
        uint32_t p = Ab + (uint32_t)((r0 + gid) * ASTRIDE + c + tig) * 4u;
        f[0] = lds32(p);
        f[1] = lds32(p + 8u * ASTRIDE * 4u);
        f[2] = lds32(p + 16u);
        f[3] = lds32(p + 8u * ASTRIDE * 4u + 16u);
    };

    // ---------------- prologue ----------------
    prefetch(A1, Hin);                       // H[k=0] -> A1 (async)

    // stage vt tile synchronously into A0 (raw; rounding at frag load)
    {
        const float4* vp = (const float4*)vt;
#pragma unroll
        for (int j = 0; j < 16; j++) {
            int idx = j * 256 + tid;
            int row = idx >> 5, ch = idx & 31;
            int node = base + row;
            float4 v = make_float4(0.f, 0.f, 0.f, 0.f);
            if (node < Nn) v = vp[(size_t)node * 32 + ch];
            sts128(A0 + (uint32_t)(row * ASTRIDE + ch * 4) * 4u, v);
        }
    }
    __syncthreads();

    // gk fragments (register-resident): gkf[mt][n][4] for this warp's rows /
    // its 4 n-tiles of GD
    float gkf[2][4][4];
#pragma unroll
    for (int mt = 0; mt < 2; mt++)
#pragma unroll
        for (int n = 0; n < 4; n++)
#pragma unroll
            for (int q = 0; q < 4; q++) gkf[mt][n][q] = 0.f;
#pragma unroll
    for (int kt = 0; kt < 16; kt++) {
        uint32_t a0[4], a1[4];
        {
            float f[4]; ldaf(f, A0, wrow * 32, kt * 8);
            a0[0] = tf32u(f[0]); a0[1] = tf32u(f[1]); a0[2] = tf32u(f[2]); a0[3] = tf32u(f[3]);
        }
        {
            float f[4]; ldaf(f, A0, wrow * 32 + 16, kt * 8);
            a1[0] = tf32u(f[0]); a1[1] = tf32u(f[1]); a1[2] = tf32u(f[2]); a1[3] = tf32u(f[3]);
        }
        const float2* bp = WgvF + (kt * 8 + nhalf * 4) * 32 + lane;
#pragma unroll
        for (int n = 0; n < 4; n++) {
            float2 b = __ldg(bp + n * 32);
            uint32_t b0 = __float_as_uint(b.x), b1 = __float_as_uint(b.y);
            mma8(gkf[0][n], a0, b0, b1);
            mma8(gkf[1][n], a1, b0, b1);
        }
    }
    asm volatile("cp.async.wait_group 0;" ::: "memory");
    __syncthreads();                          // A1 ready; A0 free

    // ---------------- main loop ----------------
    float uacc[2][8][4];
#pragma unroll
    for (int mt = 0; mt < 2; mt++)
#pragma unroll
        for (int n = 0; n < 8; n++)
#pragma unroll
            for (int q = 0; q < 4; q++) uacc[mt][n][q] = 0.f;
    float Z[2][2] = {{0.f, 0.f}, {0.f, 0.f}};

    for (int k = 0; k < KH; k++) {
        const uint32_t cur = (k & 1) ? A0 : A1;
        const uint32_t nxt = (k & 1) ? A1 : A0;
        if (k + 1 < KH) prefetch(nxt, Hin + (size_t)(k + 1) * (size_t)Nn * HD);

        // ---- GEMM1: partial g_query . g_key for this warp's n-half ----
        float c[2][4][4];
#pragma unroll
        for (int mt = 0; mt < 2; mt++)
#pragma unroll
            for (int n = 0; n < 4; n++)
#pragma unroll
                for (int q = 0; q < 4; q++) c[mt][n][q] = 0.f;
#pragma unroll
        for (int kt = 0; kt < 16; kt++) {
            uint32_t a0[4], a1[4];
            {
                float f[4]; ldaf(f, cur, wrow * 32, kt * 8);
                a0[0] = tf32u(f[0]); a0[1] = tf32u(f[1]); a0[2] = tf32u(f[2]); a0[3] = tf32u(f[3]);
            }
            {
                float f[4]; ldaf(f, cur, wrow * 32 + 16, kt * 8);
                a1[0] = tf32u(f[0]); a1[1] = tf32u(f[1]); a1[2] = tf32u(f[2]); a1[3] = tf32u(f[3]);
            }
            const float2* bp = WghF + k * 4096 + (kt * 8 + nhalf * 4) * 32 + lane;
#pragma unroll
            for (int n = 0; n < 4; n++) {
                float2 b = __ldg(bp + n * 32);
                uint32_t b0 = __float_as_uint(b.x), b1 = __float_as_uint(b.y);
                mma8(c[0][n], a0, b0, b1);
                mma8(c[1][n], a1, b0, b1);
            }
        }
#pragma unroll
        for (int mt = 0; mt < 2; mt++) {
            float d0 = 0.f, d1 = 0.f;
#pragma unroll
            for (int n = 0; n < 4; n++) {
                d0 = fmaf(c[mt][n][0], gkf[mt][n][0], fmaf(c[mt][n][1], gkf[mt][n][1], d0));
                d1 = fmaf(c[mt][n][2], gkf[mt][n][2], fmaf(c[mt][n][3], gkf[mt][n][3], d1));
            }
            d0 += __shfl_xor_sync(0xffffffffu, d0, 1);
            d0 += __shfl_xor_sync(0xffffffffu, d0, 2);
            d1 += __shfl_xor_sync(0xffffffffu, d1, 1);
            d1 += __shfl_xor_sync(0xffffffffu, d1, 2);
            if (tig == 0) {
                int row = wrow * 32 + mt * 16 + gid;
                sts32(DS + (uint32_t)(nhalf * 128 + row) * 4u, d0);
                sts32(DS + (uint32_t)(nhalf * 128 + row + 8) * 4u, d1);
            }
        }
        __syncthreads();

        // ---- combine halves -> w per row ----
        float wgt[2][2];
#pragma unroll
        for (int mt = 0; mt < 2; mt++) {
            int row = wrow * 32 + mt * 16 + gid;
            float d0 = lds32(DS + (uint32_t)row * 4u) + lds32(DS + (uint32_t)(128 + row) * 4u);
            float d1 = lds32(DS + (uint32_t)(row + 8) * 4u) + lds32(DS + (uint32_t)(128 + row + 8) * 4u);
            float l0 = d0 >= 0.f ? d0 : 0.01f * d0;
            float l1 = d1 >= 0.f ? d1 : 0.01f * d1;
            wgt[mt][0] = __expf(l0 * 0.125f);
            wgt[mt][1] = __expf(l1 * 0.125f);
            Z[mt][0] += wgt[mt][0];
            Z[mt][1] += wgt[mt][1];
        }

        // ---- GEMM2: U += (w .* H) @ Wuh[k], this warp's n-half ----
#pragma unroll
        for (int kt = 0; kt < 16; kt++) {
            uint32_t a0[4], a1[4];
            {
                float f[4]; ldaf(f, cur, wrow * 32, kt * 8);
                a0[0] = tf32u(f[0] * wgt[0][0]); a0[1] = tf32u(f[1] * wgt[0][1]);
                a0[2] = tf32u(f[2] * wgt[0][0]); a0[3] = tf32u(f[3] * wgt[0][1]);
            }
            {
                float f[4]; ldaf(f, cur, wrow * 32 + 16, kt * 8);
                a1[0] = tf32u(f[0] * wgt[1][0]); a1[1] = tf32u(f[1] * wgt[1][1]);
                a1[2] = tf32u(f[2] * wgt[1][0]); a1[3] = tf32u(f[3] * wgt[1][1]);
            }
            const float2* bp = WuhF + k * 8192 + (kt * 16 + nhalf * 8) * 32 + lane;
#pragma unroll
            for (int n = 0; n < 8; n++) {
                float2 b = __ldg(bp + n * 32);
                uint32_t b0 = __float_as_uint(b.x), b1 = __float_as_uint(b.y);
                mma8(uacc[0][n], a0, b0, b1);
                mma8(uacc[1][n], a1, b0, b1);
            }
        }

        asm volatile("cp.async.wait_group 0;" ::: "memory");
        __syncthreads();
    }

    // ---------------- epilogue ----------------
#pragma unroll
    for (int mt = 0; mt < 2; mt++) {
        float inv0 = 1.0f / Z[mt][0];
        float inv1 = 1.0f / Z[mt][1];
        int node0 = base + wrow * 32 + mt * 16 + gid;
        int node1 = node0 + 8;
        if (node0 < Nn) {
            float2* op = (float2*)(out + (size_t)node0 * HD + nhalf * 64);
#pragma unroll
            for (int n = 0; n < 8; n++) {
                float v0 = uacc[mt][n][0] * inv0;
                float v1 = uacc[mt][n][1] * inv0;
                float2 o;
                o.x = v0 >= 0.f ? v0 : 0.01f * v0;
                o.y = v1 >= 0.f ? v1 : 0.01f * v1;
                op[n * 4 + tig] = o;
            }
        }
        if (node1 < Nn) {
            float2* op = (float2*)(out + (size_t)node1 * HD + nhalf * 64);
#pragma unroll
            for (int n = 0; n < 8; n++) {
                float v0 = uacc[mt][n][2] * inv1;
                float v1 = uacc[mt][n][3] * inv1;
                float2 o;
                o.x = v0 >= 0.f ? v0 : 0.01f * v0;
                o.y = v1 >= 0.f ? v1 : 0.01f * v1;
                op[n * 4 + tig] = o;
            }
        }
    }
}

// ---------------- launch ----------------
extern "C" void kernel_launch(void* const* d_in, const int* in_sizes, int n_in,
                              void* d_out, int out_size) {
    const float* vt  = (const float*)d_in[0];
    const float* H   = (const float*)d_in[1];
    const float* Wgv = (const float*)d_in[2];
    const float* Wgh = (const float*)d_in[3];
    const float* Wuh = (const float*)d_in[4];
    float* out = (float*)d_out;

    int Nn = in_sizes[0] / HD;

    cudaFuncSetAttribute(het_main, cudaFuncAttributeMaxDynamicSharedMemorySize, SMEM_TOTAL);

    int total = 4096 + KH * 4096 + KH * 8192;
    prep_kernel<<<(total + 255) / 256, 256>>>(Wgv, Wgh, Wuh);

    int blocks = (Nn + 127) / 128;
    het_main<<<blocks, 256, SMEM_TOTAL>>>(vt, H, out, Nn);
}

// round 5
// speedup vs baseline: 2.1874x; 1.0406x over previous
#include <cuda_runtime.h>
#include <cstdint>

// GraphHeteroAtt via mma.sync m16n8k8 tf32 (compute_103-safe).
// U[n] = lrelu( (sum_k w_k[n] * H[k,n,:] @ Wuh[k]) / (sum_k w_k[n]) )
// w_k[n] = exp(lrelu( (H[k,n,:]@Wgh[k]) . (vt[n,:]@Wgv) ) / 8)
//
// CTA = 64 nodes, 256 threads (8 warps) = 2 row-groups x 4 n-quarters.
// 2 CTAs/SM (66.5KB smem, <=128 regs). H tiles double-buffered cp.async.
// A-fragments via ldmatrix.x4 on XOR-swizzled 32KB tiles.

#define KH 8
#define HD 128
#define GD 64

// ---------------- helpers ----------------
__device__ __forceinline__ uint32_t smem_u32(const void* p) {
    uint32_t a;
    asm("{ .reg .u64 t; cvta.to.shared.u64 t, %1; cvt.u32.u64 %0, t; }"
        : "=r"(a) : "l"(p));
    return a;
}
__device__ __forceinline__ float tf32r(float x) {
    uint32_t u;
    asm("cvt.rna.tf32.f32 %0, %1;" : "=r"(u) : "f"(x));
    return __uint_as_float(u);
}
__device__ __forceinline__ uint32_t tf32u(float x) {
    uint32_t u;
    asm("cvt.rna.tf32.f32 %0, %1;" : "=r"(u) : "f"(x));
    return u;
}
__device__ __forceinline__ void sts128(uint32_t a, float4 v) {
    asm volatile("st.shared.v4.f32 [%0], {%1, %2, %3, %4};"
                 :: "r"(a), "f"(v.x), "f"(v.y), "f"(v.z), "f"(v.w) : "memory");
}
__device__ __forceinline__ void sts32(uint32_t a, float v) {
    asm volatile("st.shared.f32 [%0], %1;" :: "r"(a), "f"(v) : "memory");
}
__device__ __forceinline__ float lds32(uint32_t a) {
    float v;
    asm volatile("ld.shared.f32 %0, [%1];" : "=f"(v) : "r"(a));
    return v;
}
__device__ __forceinline__ void ldsm4(uint32_t r[4], uint32_t a) {
    asm volatile("ldmatrix.sync.aligned.m8n8.x4.shared.b16 {%0,%1,%2,%3}, [%4];"
                 : "=r"(r[0]), "=r"(r[1]), "=r"(r[2]), "=r"(r[3]) : "r"(a));
}
__device__ __forceinline__ void mma8(float c[4], const uint32_t a[4], uint32_t b0, uint32_t b1) {
    asm volatile(
        "mma.sync.aligned.m16n8k8.row.col.f32.tf32.tf32.f32 "
        "{%0,%1,%2,%3}, {%4,%5,%6,%7}, {%8,%9}, {%0,%1,%2,%3};"
        : "+f"(c[0]), "+f"(c[1]), "+f"(c[2]), "+f"(c[3])
        : "r"(a[0]), "r"(a[1]), "r"(a[2]), "r"(a[3]), "r"(b0), "r"(b1));
}

// ---------------- fragment-ordered weights (float4 = 2 adjacent n-tiles) ----------------
// Per (kt, npair, lane): (b0_nt0, b1_nt0, b0_nt1, b1_nt1) with nt = npair*2 (+1),
// b0 = B[kt*8+tig][nt*8+gid], b1 = B[kt*8+tig+4][nt*8+gid].
__device__ float4 WgvF[2048];          // 16 kt * 4 npair * 32
__device__ float4 WghF[KH * 2048];
__device__ float4 WuhF[KH * 4096];     // 16 kt * 8 npair * 32

__global__ void prep_kernel(const float* __restrict__ Wgv,
                            const float* __restrict__ Wgh,
                            const float* __restrict__ Wuh) {
    int i = blockIdx.x * 256 + threadIdx.x;
    if (i < 2048) {
        int p = i;
        int kt = p >> 7, npair = (p >> 5) & 3, lane = p & 31;
        int gid = lane >> 2, tig = lane & 3;
        int r0 = kt * 8 + tig;
        int c0 = (npair * 2) * 8 + gid, c1 = (npair * 2 + 1) * 8 + gid;
        WgvF[p] = make_float4(tf32r(Wgv[r0 * GD + c0]), tf32r(Wgv[(r0 + 4) * GD + c0]),
                              tf32r(Wgv[r0 * GD + c1]), tf32r(Wgv[(r0 + 4) * GD + c1]));
    } else if (i < 2048 + KH * 2048) {
        int j = i - 2048;
        int k = j >> 11, p = j & 2047;
        int kt = p >> 7, npair = (p >> 5) & 3, lane = p & 31;
        int gid = lane >> 2, tig = lane & 3;
        int r0 = kt * 8 + tig;
        int c0 = (npair * 2) * 8 + gid, c1 = (npair * 2 + 1) * 8 + gid;
        const float* b = Wgh + k * HD * GD;
        WghF[k * 2048 + p] = make_float4(tf32r(b[r0 * GD + c0]), tf32r(b[(r0 + 4) * GD + c0]),
                                         tf32r(b[r0 * GD + c1]), tf32r(b[(r0 + 4) * GD + c1]));
    } else if (i < 2048 + KH * 2048 + KH * 4096) {
        int j = i - 2048 - KH * 2048;
        int k = j >> 12, p = j & 4095;
        int kt = p >> 8, npair = (p >> 5) & 7, lane = p & 31;
        int gid = lane >> 2, tig = lane & 3;
        int r0 = kt * 8 + tig;
        int c0 = (npair * 2) * 8 + gid, c1 = (npair * 2 + 1) * 8 + gid;
        const float* b = Wuh + k * HD * HD;
        WuhF[k * 4096 + p] = make_float4(tf32r(b[r0 * HD + c0]), tf32r(b[(r0 + 4) * HD + c0]),
                                         tf32r(b[r0 * HD + c1]), tf32r(b[(r0 + 4) * HD + c1]));
    }
}

// ---------------- smem layout ----------------
// A0 @ 0     : 64 rows x 512 B (XOR-swizzled 16B chunks) = 32768
// A1 @ 32768 : 32768
// DS @ 65536 : 4 n-quarter partials x 64 rows x 4B = 1024
#define ABUF_BYTES 32768u
#define SMEM_DS    65536u
#define SMEM_TOTAL 66560u

__global__ void __launch_bounds__(256, 2)
het_main(const float* __restrict__ vt, const float* __restrict__ Hin,
         float* __restrict__ out, int Nn) {
    extern __shared__ char smem_raw[];
    const uint32_t A0 = smem_u32(smem_raw);
    const uint32_t A1 = A0 + ABUF_BYTES;
    const uint32_t DS = A0 + SMEM_DS;

    const int tid  = threadIdx.x;
    const int warp = tid >> 5;
    const int lane = tid & 31;
    const int gid  = lane >> 2;
    const int tig  = lane & 3;
    const int rg   = warp >> 2;      // row group (32 rows each)
    const int q    = warp & 3;       // n-quarter
    const int base = blockIdx.x << 6;

    // ldmatrix lane addressing: tile t=lane>>3 -> {a0: r0-7/c0-3, a1: r8-15/c0-3,
    // a2: r0-7/c4-7, a3: r8-15/c4-7}
    const int tsel = lane >> 3;
    const int trow = lane & 7;
    const int csel = tsel >> 1;                    // 16B-chunk offset within kt
    const int rsub = ((tsel & 1) << 3) + trow;     // row within m16 tile
    const uint32_t rowoff0 = (uint32_t)(rg * 32 + rsub) * 512u;
    const uint32_t rowoff1 = rowoff0 + 16u * 512u;

    auto phys = [&](int kt) -> uint32_t {
        return (uint32_t)(((kt * 2 + csel) ^ trow) << 4);
    };

    // async prefetch of one 64x128 tile into buffer Ab (swizzled)
    auto prefetch = [&](uint32_t Ab, const float* src) {
#pragma unroll
        for (int j = 0; j < 8; j++) {
            int idx = j * 256 + tid;
            int row = idx >> 5, ch = idx & 31;
            int node = base + row;
            const float* s = src + (size_t)(node < Nn ? node : 0) * HD + ch * 4;
            uint32_t d = Ab + (uint32_t)row * 512u + (uint32_t)((ch ^ (row & 7)) << 4);
            int sz = (node < Nn) ? 16 : 0;
            asm volatile("cp.async.cg.shared.global [%0], [%1], 16, %2;"
                         :: "r"(d), "l"(s), "r"(sz) : "memory");
        }
        asm volatile("cp.async.commit_group;" ::: "memory");
    };

    // ---------------- prologue ----------------
    prefetch(A1, Hin);                      // H[k=0] -> A1 (async)

    {   // stage vt tile synchronously into A0 (raw f32)
        const float4* vp = (const float4*)vt;
#pragma unroll
        for (int j = 0; j < 8; j++) {
            int idx = j * 256 + tid;
            int row = idx >> 5, ch = idx & 31;
            int node = base + row;
            float4 v = make_float4(0.f, 0.f, 0.f, 0.f);
            if (node < Nn) v = vp[(size_t)node * 32 + ch];
            sts128(A0 + (uint32_t)row * 512u + (uint32_t)((ch ^ (row & 7)) << 4), v);
        }
    }
    __syncthreads();

    // gk fragments: this warp's 32 rows x its 16 GD-cols (2 n-tiles)
    float gkf[2][2][4];
#pragma unroll
    for (int mt = 0; mt < 2; mt++)
#pragma unroll
        for (int n = 0; n < 2; n++)
#pragma unroll
            for (int qq = 0; qq < 4; qq++) gkf[mt][n][qq] = 0.f;
#pragma unroll
    for (int kt = 0; kt < 16; kt++) {
        uint32_t r0[4], r1[4], a0[4], a1[4];
        ldsm4(r0, A0 + rowoff0 + phys(kt));
        ldsm4(r1, A0 + rowoff1 + phys(kt));
#pragma unroll
        for (int i = 0; i < 4; i++) {
            a0[i] = tf32u(__uint_as_float(r0[i]));
            a1[i] = tf32u(__uint_as_float(r1[i]));
        }
        float4 b = __ldg(&WgvF[(kt * 4 + q) * 32 + lane]);
        uint32_t b0 = __float_as_uint(b.x), b1 = __float_as_uint(b.y);
        uint32_t b2 = __float_as_uint(b.z), b3 = __float_as_uint(b.w);
        mma8(gkf[0][0], a0, b0, b1);  mma8(gkf[0][1], a0, b2, b3);
        mma8(gkf[1][0], a1, b0, b1);  mma8(gkf[1][1], a1, b2, b3);
    }
    asm volatile("cp.async.wait_group 0;" ::: "memory");
    __syncthreads();                         // A1 ready; A0 free

    // ---------------- main loop ----------------
    float uacc[2][4][4];
#pragma unroll
    for (int mt = 0; mt < 2; mt++)
#pragma unroll
        for (int n = 0; n < 4; n++)
#pragma unroll
            for (int qq = 0; qq < 4; qq++) uacc[mt][n][qq] = 0.f;
    float Z[2][2] = {{0.f, 0.f}, {0.f, 0.f}};

    for (int k = 0; k < KH; k++) {
        const uint32_t cur = (k & 1) ? A0 : A1;
        const uint32_t nxt = (k & 1) ? A1 : A0;
        if (k + 1 < KH) prefetch(nxt, Hin + (size_t)(k + 1) * (size_t)Nn * HD);

        // ---- GEMM1: g_query partials over this warp's 16 GD-cols ----
        float c[2][2][4];
#pragma unroll
        for (int mt = 0; mt < 2; mt++)
#pragma unroll
            for (int n = 0; n < 2; n++)
#pragma unroll
                for (int qq = 0; qq < 4; qq++) c[mt][n][qq] = 0.f;
#pragma unroll
        for (int kt = 0; kt < 16; kt++) {
            uint32_t r0[4], r1[4], a0[4], a1[4];
            ldsm4(r0, cur + rowoff0 + phys(kt));
            ldsm4(r1, cur + rowoff1 + phys(kt));
#pragma unroll
            for (int i = 0; i < 4; i++) {
                a0[i] = tf32u(__uint_as_float(r0[i]));
                a1[i] = tf32u(__uint_as_float(r1[i]));
            }
            float4 b = __ldg(&WghF[k * 2048 + (kt * 4 + q) * 32 + lane]);
            uint32_t b0 = __float_as_uint(b.x), b1 = __float_as_uint(b.y);
            uint32_t b2 = __float_as_uint(b.z), b3 = __float_as_uint(b.w);
            mma8(c[0][0], a0, b0, b1);  mma8(c[0][1], a0, b2, b3);
            mma8(c[1][0], a1, b0, b1);  mma8(c[1][1], a1, b2, b3);
        }
        // partial dot with gk over this warp's cols, reduce over lanes in tig
#pragma unroll
        for (int mt = 0; mt < 2; mt++) {
            float d0 = 0.f, d1 = 0.f;
#pragma unroll
            for (int n = 0; n < 2; n++) {
                d0 = fmaf(c[mt][n][0], gkf[mt][n][0], fmaf(c[mt][n][1], gkf[mt][n][1], d0));
                d1 = fmaf(c[mt][n][2], gkf[mt][n][2], fmaf(c[mt][n][3], gkf[mt][n][3], d1));
            }
            d0 += __shfl_xor_sync(0xffffffffu, d0, 1);
            d0 += __shfl_xor_sync(0xffffffffu, d0, 2);
            d1 += __shfl_xor_sync(0xffffffffu, d1, 1);
            d1 += __shfl_xor_sync(0xffffffffu, d1, 2);
            if (tig == 0) {
                int row = rg * 32 + mt * 16 + gid;
                sts32(DS + (uint32_t)(q * 64 + row) * 4u, d0);
                sts32(DS + (uint32_t)(q * 64 + row + 8) * 4u, d1);
            }
        }
        __syncthreads();

        // ---- combine quarters -> w per row ----
        float wgt[2][2];
#pragma unroll
        for (int mt = 0; mt < 2; mt++) {
            int row = rg * 32 + mt * 16 + gid;
            float d0 = lds32(DS + (uint32_t)row * 4u)
                     + lds32(DS + (uint32_t)(64 + row) * 4u)
                     + lds32(DS + (uint32_t)(128 + row) * 4u)
                     + lds32(DS + (uint32_t)(192 + row) * 4u);
            float d1 = lds32(DS + (uint32_t)(row + 8) * 4u)
                     + lds32(DS + (uint32_t)(64 + row + 8) * 4u)
                     + lds32(DS + (uint32_t)(128 + row + 8) * 4u)
                     + lds32(DS + (uint32_t)(192 + row + 8) * 4u);
            float l0 = d0 >= 0.f ? d0 : 0.01f * d0;
            float l1 = d1 >= 0.f ? d1 : 0.01f * d1;
            wgt[mt][0] = __expf(l0 * 0.125f);
            wgt[mt][1] = __expf(l1 * 0.125f);
            Z[mt][0] += wgt[mt][0];
            Z[mt][1] += wgt[mt][1];
        }

        // ---- GEMM2: U += (w .* H) @ Wuh[k], this warp's 32 output cols ----
#pragma unroll
        for (int kt = 0; kt < 16; kt++) {
            uint32_t r0[4], r1[4], a0[4], a1[4];
            ldsm4(r0, cur + rowoff0 + phys(kt));
            ldsm4(r1, cur + rowoff1 + phys(kt));
            a0[0] = tf32u(__uint_as_float(r0[0]) * wgt[0][0]);
            a0[1] = tf32u(__uint_as_float(r0[1]) * wgt[0][1]);
            a0[2] = tf32u(__uint_as_float(r0[2]) * wgt[0][0]);
            a0[3] = tf32u(__uint_as_float(r0[3]) * wgt[0][1]);
            a1[0] = tf32u(__uint_as_float(r1[0]) * wgt[1][0]);
            a1[1] = tf32u(__uint_as_float(r1[1]) * wgt[1][1]);
            a1[2] = tf32u(__uint_as_float(r1[2]) * wgt[1][0]);
            a1[3] = tf32u(__uint_as_float(r1[3]) * wgt[1][1]);
            const float4* bp = &WuhF[k * 4096 + (kt * 8 + q * 2) * 32 + lane];
            float4 bA = __ldg(bp);
            float4 bB = __ldg(bp + 32);
            uint32_t u0 = __float_as_uint(bA.x), u1 = __float_as_uint(bA.y);
            uint32_t u2 = __float_as_uint(bA.z), u3 = __float_as_uint(bA.w);
            uint32_t u4 = __float_as_uint(bB.x), u5 = __float_as_uint(bB.y);
            uint32_t u6 = __float_as_uint(bB.z), u7 = __float_as_uint(bB.w);
            mma8(uacc[0][0], a0, u0, u1);  mma8(uacc[0][1], a0, u2, u3);
            mma8(uacc[0][2], a0, u4, u5);  mma8(uacc[0][3], a0, u6, u7);
            mma8(uacc[1][0], a1, u0, u1);  mma8(uacc[1][1], a1, u2, u3);
            mma8(uacc[1][2], a1, u4, u5);  mma8(uacc[1][3], a1, u6, u7);
        }

        asm volatile("cp.async.wait_group 0;" ::: "memory");
        __syncthreads();
    }

    // ---------------- epilogue ----------------
#pragma unroll
    for (int mt = 0; mt < 2; mt++) {
        float inv0 = 1.0f / Z[mt][0];
        float inv1 = 1.0f / Z[mt][1];
        int node0 = base + rg * 32 + mt * 16 + gid;
        int node1 = node0 + 8;
        if (node0 < Nn) {
            float2* op = (float2*)(out + (size_t)node0 * HD + q * 32);
#pragma unroll
            for (int n = 0; n < 4; n++) {
                float v0 = uacc[mt][n][0] * inv0;
                float v1 = uacc[mt][n][1] * inv0;
                float2 o;
                o.x = v0 >= 0.f ? v0 : 0.01f * v0;
                o.y = v1 >= 0.f ? v1 : 0.01f * v1;
                op[n * 4 + tig] = o;
            }
        }
        if (node1 < Nn) {
            float2* op = (float2*)(out + (size_t)node1 * HD + q * 32);
#pragma unroll
            for (int n = 0; n < 4; n++) {
                float v0 = uacc[mt][n][2] * inv1;
                float v1 = uacc[mt][n][3] * inv1;
                float2 o;
                o.x = v0 >= 0.f ? v0 : 0.01f * v0;
                o.y = v1 >= 0.f ? v1 : 0.01f * v1;
                op[n * 4 + tig] = o;
            }
        }
    }
}

// ---------------- launch ----------------
extern "C" void kernel_launch(void* const* d_in, const int* in_sizes, int n_in,
                              void* d_out, int out_size) {
    const float* vt  = (const float*)d_in[0];
    const float* H   = (const float*)d_in[1];
    const float* Wgv = (const float*)d_in[2];
    const float* Wgh = (const float*)d_in[3];
    const float* Wuh = (const float*)d_in[4];
    float* out = (float*)d_out;

    int Nn = in_sizes[0] / HD;

    cudaFuncSetAttribute(het_main, cudaFuncAttributeMaxDynamicSharedMemorySize, SMEM_TOTAL);

    int total = 2048 + KH * 2048 + KH * 4096;   // 51200 prep threads
    prep_kernel<<<(total + 255) / 256, 256>>>(Wgv, Wgh, Wuh);

    int blocks = (Nn + 63) / 64;
    het_main<<<blocks, 256, SMEM_TOTAL>>>(vt, H, out, Nn);
}